// round 10
// baseline (speedup 1.0000x reference)
#include <cuda_runtime.h>
#include <math.h>

#define Bb 4
#define Ss 1024
#define Ee 256
#define Hh 8
#define Dd 32
#define TOK (Bb*Ss)
#define QB 32
#define RS 768          // fused QKV row stride
#define CT 256          // attention col tile
#define TP 1032         // padded T row
#define KSST 36         // K-tile smem stride (floats)
#define VTST 260        // transposed V-tile stride
#define QEST 33         // Qe stride
#define REDW 1056       // 32*33 per-warp reduction slab
#define AST 20          // GEMM A-tile stride [m][k]
#define BST 72          // GEMM B-tile stride [k][n]

// ---------------- scratch ----------------
__device__ float g_QKV[TOK*RS];
__device__ float g_H[TOK*(Ee/2)];
__device__ float g_O[TOK*2*Hh];
__device__ float g_A[TOK*Ee];

// ---------------- tf32 helpers ----------------
__device__ __forceinline__ void tf32split(float x, unsigned &hi, unsigned &lo) {
    unsigned h; asm("cvt.rna.tf32.f32 %0, %1;" : "=r"(h) : "f"(x));
    float r = x - __uint_as_float(h);
    unsigned l; asm("cvt.rna.tf32.f32 %0, %1;" : "=r"(l) : "f"(r));
    hi = h; lo = l;
}

__device__ __forceinline__ void mma_tf32(float* d, const unsigned* a, unsigned b0, unsigned b1) {
    asm volatile("mma.sync.aligned.m16n8k8.row.col.f32.tf32.tf32.f32 "
        "{%0,%1,%2,%3},{%4,%5,%6,%7},{%8,%9},{%0,%1,%2,%3};"
        : "+f"(d[0]), "+f"(d[1]), "+f"(d[2]), "+f"(d[3])
        : "r"(a[0]), "r"(a[1]), "r"(a[2]), "r"(a[3]), "r"(b0), "r"(b1));
}

// ---------------- tf32 MMA GEMM core (64x64 tile, K multiple of 16) ----------------
// 8 warps: warp w -> m-block (w&3)*16, n-block (w>>2)*32 (4 n8 groups)
struct MmaAcc { float a[4][4]; };

__device__ __forceinline__ void mma_gemm_core(
    const float* __restrict__ A, int lda, int m0,
    const float* __restrict__ B, int ldb, int n0,
    int K, float* As, float* Bs, MmaAcc& acc)
{
    const int tid = threadIdx.x;
    const int lane = tid & 31;
    const int w = tid >> 5;
    const int g = lane >> 2, td = lane & 3;
    const int wm = (w & 3) * 16, wn = (w >> 2) * 32;

    const int arow = tid >> 2, ak4 = (tid & 3) * 4;
    const int brow = tid >> 4, bn4 = (tid & 15) * 4;

    #pragma unroll
    for (int ng = 0; ng < 4; ++ng)
        #pragma unroll
        for (int r = 0; r < 4; ++r) acc.a[ng][r] = 0.f;

    float4 aPre = *(const float4*)&A[(size_t)(m0 + arow) * lda + ak4];
    float4 bPre = *(const float4*)&B[(size_t)brow * ldb + n0 + bn4];

    for (int k0 = 0; k0 < K; k0 += 16) {
        *(float4*)&As[arow*AST + ak4] = aPre;
        *(float4*)&Bs[brow*BST + bn4] = bPre;
        __syncthreads();
        if (k0 + 16 < K) {
            aPre = *(const float4*)&A[(size_t)(m0 + arow) * lda + k0 + 16 + ak4];
            bPre = *(const float4*)&B[(size_t)(k0 + 16 + brow) * ldb + n0 + bn4];
        }
        #pragma unroll
        for (int ks = 0; ks < 2; ++ks) {
            unsigned ah[4], al[4];
            {
                float a0 = As[(wm + g    )*AST + ks*8 + td];
                float a1 = As[(wm + g + 8)*AST + ks*8 + td];
                float a2 = As[(wm + g    )*AST + ks*8 + td + 4];
                float a3 = As[(wm + g + 8)*AST + ks*8 + td + 4];
                tf32split(a0, ah[0], al[0]);
                tf32split(a1, ah[1], al[1]);
                tf32split(a2, ah[2], al[2]);
                tf32split(a3, ah[3], al[3]);
            }
            #pragma unroll
            for (int ng = 0; ng < 4; ++ng) {
                float b0f = Bs[(ks*8 + td    )*BST + wn + ng*8 + g];
                float b1f = Bs[(ks*8 + td + 4)*BST + wn + ng*8 + g];
                unsigned bh0, bl0, bh1, bl1;
                tf32split(b0f, bh0, bl0);
                tf32split(b1f, bh1, bl1);
                mma_tf32(acc.a[ng], ah, bh0, bh1);
                mma_tf32(acc.a[ng], ah, bl0, bl1);
                mma_tf32(acc.a[ng], al, bh0, bh1);
            }
        }
        __syncthreads();
    }
}

// ---------------- fused QKV + MLP1 GEMM (tf32 MMA) ----------------
// grid (14, TOK/64): nb 0..11 -> QKV, nb 12..13 -> MLP1 (bias+gelu)
__global__ __launch_bounds__(256)
void qkv_mlp_kernel(const float* __restrict__ x,
                    const float* __restrict__ Wq, const float* __restrict__ Wk,
                    const float* __restrict__ Wv, const float* __restrict__ W1,
                    const float* __restrict__ b1,
                    float* __restrict__ QKV, float* __restrict__ Hout)
{
    __shared__ float As[64*AST];
    __shared__ float Bs[16*BST];
    const int tid = threadIdx.x;
    const int lane = tid & 31;
    const int w = tid >> 5;
    const int g = lane >> 2, td = lane & 3;
    const int wm = (w & 3) * 16, wn = (w >> 2) * 32;
    const int nb = blockIdx.x;
    const int m0 = blockIdx.y * 64;

    const float* Bp; int bn0, BN;
    if (nb < 12) { Bp = (nb < 4 ? Wq : (nb < 8 ? Wk : Wv)); bn0 = (nb & 3) * 64; BN = 256; }
    else         { Bp = W1; bn0 = (nb - 12) * 64; BN = 128; }

    MmaAcc acc;
    mma_gemm_core(x, 256, m0, Bp, BN, bn0, 256, As, Bs, acc);

    if (nb < 12) {
        #pragma unroll
        for (int ng = 0; ng < 4; ++ng) {
            int col = nb*64 + wn + ng*8 + 2*td;
            int r0 = m0 + wm + g;
            *(float2*)&QKV[(size_t)r0      *RS + col] = make_float2(acc.a[ng][0], acc.a[ng][1]);
            *(float2*)&QKV[(size_t)(r0 + 8)*RS + col] = make_float2(acc.a[ng][2], acc.a[ng][3]);
        }
    } else {
        #pragma unroll
        for (int ng = 0; ng < 4; ++ng) {
            int n = (nb - 12)*64 + wn + ng*8 + 2*td;
            int r0 = m0 + wm + g;
            float bv0 = b1[n], bv1 = b1[n + 1];
            float v[4] = {acc.a[ng][0] + bv0, acc.a[ng][1] + bv1,
                          acc.a[ng][2] + bv0, acc.a[ng][3] + bv1};
            #pragma unroll
            for (int r = 0; r < 4; ++r)
                v[r] = 0.5f * v[r] * (1.0f + erff(v[r] * 0.70710678118654752440f));
            *(float2*)&Hout[(size_t)r0      *128 + n] = make_float2(v[0], v[1]);
            *(float2*)&Hout[(size_t)(r0 + 8)*128 + n] = make_float2(v[2], v[3]);
        }
    }
}

// ---------------- out-proj GEMM (tf32 MMA): C = A@B + bias, N mult of 64 ----------------
__global__ __launch_bounds__(256)
void mma_gemm_bias(const float* __restrict__ A, const float* __restrict__ B,
                   const float* __restrict__ bias, float* __restrict__ C,
                   int N, int K)
{
    __shared__ float As[64*AST];
    __shared__ float Bs[16*BST];
    const int tid = threadIdx.x;
    const int lane = tid & 31;
    const int w = tid >> 5;
    const int g = lane >> 2, td = lane & 3;
    const int wm = (w & 3) * 16, wn = (w >> 2) * 32;
    const int m0 = blockIdx.y * 64;
    const int n0 = blockIdx.x * 64;

    MmaAcc acc;
    mma_gemm_core(A, K, m0, B, N, n0, K, As, Bs, acc);

    #pragma unroll
    for (int ng = 0; ng < 4; ++ng) {
        int col = n0 + wn + ng*8 + 2*td;
        int r0 = m0 + wm + g;
        float bv0 = bias[col], bv1 = bias[col + 1];
        *(float2*)&C[(size_t)r0      *N + col] = make_float2(acc.a[ng][0] + bv0, acc.a[ng][1] + bv1);
        *(float2*)&C[(size_t)(r0 + 8)*N + col] = make_float2(acc.a[ng][2] + bv0, acc.a[ng][3] + bv1);
    }
}

// ---------------- scalar GEMM (MLP2 only, N=16) ----------------
__global__ __launch_bounds__(256)
void gemm_kernel(const float* __restrict__ A, const float* __restrict__ B,
                 const float* __restrict__ bias, float* __restrict__ C,
                 int M, int N, int K)
{
    __shared__ float As[16*64];
    __shared__ float Bs[16*64];
    const int tid = threadIdx.x;
    const int tx = tid & 15, ty = tid >> 4;
    const int m0 = blockIdx.y * 64;
    const int n0 = blockIdx.x * 64;

    const int arow = tid >> 2, ak4 = (tid & 3) * 4;
    const int brow = tid >> 4, bn4 = (tid & 15) * 4;

    float acc[4][4] = {};
    float4 aPre = *(const float4*)&A[(size_t)(m0 + arow) * K + ak4];
    float4 bPre = make_float4(0.f,0.f,0.f,0.f);
    if (n0 + bn4 < N) bPre = *(const float4*)&B[(size_t)brow * N + n0 + bn4];

    for (int k0 = 0; k0 < K; k0 += 16) {
        As[(ak4+0)*64 + arow] = aPre.x;
        As[(ak4+1)*64 + arow] = aPre.y;
        As[(ak4+2)*64 + arow] = aPre.z;
        As[(ak4+3)*64 + arow] = aPre.w;
        *(float4*)&Bs[brow*64 + bn4] = bPre;
        __syncthreads();
        if (k0 + 16 < K) {
            aPre = *(const float4*)&A[(size_t)(m0 + arow) * K + k0 + 16 + ak4];
            if (n0 + bn4 < N) bPre = *(const float4*)&B[(size_t)(k0 + 16 + brow) * N + n0 + bn4];
        }
        #pragma unroll
        for (int kk = 0; kk < 16; ++kk) {
            float4 ar = *(const float4*)&As[kk*64 + ty*4];
            float4 br = *(const float4*)&Bs[kk*64 + tx*4];
            float a4[4] = {ar.x, ar.y, ar.z, ar.w};
            float b4[4] = {br.x, br.y, br.z, br.w};
            #pragma unroll
            for (int i = 0; i < 4; ++i)
                #pragma unroll
                for (int j = 0; j < 4; ++j)
                    acc[i][j] += a4[i] * b4[j];
        }
        __syncthreads();
    }

    #pragma unroll
    for (int i = 0; i < 4; ++i) {
        int m = m0 + ty*4 + i;
        #pragma unroll
        for (int j = 0; j < 4; ++j) {
            int n = n0 + tx*4 + j;
            if (n < N) C[(size_t)m * N + n] = acc[i][j] + bias[n];
        }
    }
}

// ---------------- fused deformable attention (tf32 MMA) ----------------
__global__ __launch_bounds__(256, 1)
void attn_kernel(const float* __restrict__ QKV, const float* __restrict__ OFF,
                 float* __restrict__ Aout)
{
    extern __shared__ float sm[];
    float* T    = sm;                       // 32*TP
    float* BUF  = T + QB*TP;                // 256*KSST floats
    float* Qe   = BUF + CT*KSST;            // 32*QEST
    float* wxs  = Qe + QB*QEST;
    float* rsum = wxs + QB;
    int*   axs  = (int*)(rsum + QB);

    const int tid = threadIdx.x;
    const int nq  = Ss / QB;
    const int bh  = blockIdx.x / nq;
    const int q0  = (blockIdx.x % nq) * QB;
    const int b   = bh / Hh;
    const int h   = bh % Hh;
    const float scale = 0.17677669529663689f;

    const float* Qb = QKV + (size_t)b*Ss*RS + h*Dd;
    const float* Kb = Qb + 256;
    const float* Vb = Qb + 512;

    const int lane = tid & 31;
    const int w    = tid >> 5;
    const int g    = lane >> 2;
    const int td   = lane & 3;

    // ---- Phase 0: Qeff (row-blended, pre-scaled) + wx/ax ----
    {
        const int d = tid & 31;
        const int qq = tid >> 5;
        #pragma unroll
        for (int it = 0; it < 4; ++it) {
            int q = qq + it*8;
            int i = q0 + q;
            float ox = OFF[((size_t)(b*Ss + i)*Hh + h)*2 + 0];
            float oy = OFF[((size_t)(b*Ss + i)*Hh + h)*2 + 1];
            float fy = floorf(oy);
            float wy = oy - fy;
            int y0 = i + (int)fy, y1 = y0 + 1;
            float qv = 0.f;
            if (y0 >= 0 && y0 < Ss) qv += (1.f - wy) * Qb[(size_t)y0*RS + d];
            if (y1 >= 0 && y1 < Ss) qv += wy * Qb[(size_t)y1*RS + d];
            Qe[q*QEST + d] = qv * scale;
            if (d == 0) { float fx = floorf(ox); wxs[q] = ox - fx; axs[q] = (int)fx; }
        }
    }
    __syncthreads();

    // ---- Phase 1: T = Qe . K^T via split-tf32 mma ----
    {
        float4 pre[8];
        #pragma unroll
        for (int l = 0; l < 8; ++l) {
            int idx = tid + l*256;
            int c = idx >> 3, t = idx & 7;
            pre[l] = *(const float4*)&Kb[(size_t)c*RS + t*4];
        }
        for (int ct = 0; ct < Ss/CT; ++ct) {
            #pragma unroll
            for (int l = 0; l < 8; ++l) {
                int idx = tid + l*256;
                int c = idx >> 3, t = idx & 7;
                *(float4*)&BUF[c*KSST + t*4] = pre[l];
            }
            __syncthreads();
            if (ct + 1 < Ss/CT) {
                #pragma unroll
                for (int l = 0; l < 8; ++l) {
                    int idx = tid + l*256;
                    int c = idx >> 3, t = idx & 7;
                    pre[l] = *(const float4*)&Kb[(size_t)((ct+1)*CT + c)*RS + t*4];
                }
            }
            float acc[4][2][4];
            #pragma unroll
            for (int ng = 0; ng < 4; ++ng)
                #pragma unroll
                for (int m = 0; m < 2; ++m)
                    #pragma unroll
                    for (int r = 0; r < 4; ++r) acc[ng][m][r] = 0.f;

            #pragma unroll
            for (int ks = 0; ks < 4; ++ks) {
                unsigned ah[8], al[8];
                #pragma unroll
                for (int m = 0; m < 2; ++m) {
                    float a0 = Qe[(m*16 + g    )*QEST + ks*8 + td];
                    float a1 = Qe[(m*16 + g + 8)*QEST + ks*8 + td];
                    float a2 = Qe[(m*16 + g    )*QEST + ks*8 + td + 4];
                    float a3 = Qe[(m*16 + g + 8)*QEST + ks*8 + td + 4];
                    tf32split(a0, ah[m*4+0], al[m*4+0]);
                    tf32split(a1, ah[m*4+1], al[m*4+1]);
                    tf32split(a2, ah[m*4+2], al[m*4+2]);
                    tf32split(a3, ah[m*4+3], al[m*4+3]);
                }
                #pragma unroll
                for (int ng = 0; ng < 4; ++ng) {
                    int n0 = w*32 + ng*8;
                    float b0f = BUF[(n0 + g)*KSST + ks*8 + td];
                    float b1f = BUF[(n0 + g)*KSST + ks*8 + td + 4];
                    unsigned bh0, bl0, bh1, bl1;
                    tf32split(b0f, bh0, bl0);
                    tf32split(b1f, bh1, bl1);
                    #pragma unroll
                    for (int m = 0; m < 2; ++m) {
                        mma_tf32(acc[ng][m], ah + m*4, bh0, bh1);
                        mma_tf32(acc[ng][m], ah + m*4, bl0, bl1);
                        mma_tf32(acc[ng][m], al + m*4, bh0, bh1);
                    }
                }
            }
            #pragma unroll
            for (int ng = 0; ng < 4; ++ng) {
                int col = ct*CT + w*32 + ng*8 + 2*td;
                #pragma unroll
                for (int m = 0; m < 2; ++m) {
                    int r0 = m*16 + g;
                    *(float2*)&T[ r0     *TP + col] = make_float2(acc[ng][m][0], acc[ng][m][1]);
                    *(float2*)&T[(r0 + 8)*TP + col] = make_float2(acc[ng][m][2], acc[ng][m][3]);
                }
            }
            __syncthreads();
        }
    }

    // ---- Phase 2: shift/blend + softmax ----
    {
        #pragma unroll
        for (int it = 0; it < 4; ++it) {
            int q = w + it*8;
            float wx = wxs[q];
            int ax = axs[q];
            float* Tq = T + q*TP;
            float dv[32];
            float m = -1e30f;
            #pragma unroll
            for (int jj = 0; jj < 32; ++jj) {
                int j = lane + jj*32;
                int c0 = j + ax, c1 = c0 + 1;
                float t0 = (c0 >= 0 && c0 < Ss) ? Tq[c0] : 0.f;
                float t1 = (c1 >= 0 && c1 < Ss) ? Tq[c1] : 0.f;
                float v = (1.f - wx)*t0 + wx*t1;
                dv[jj] = v;
                m = fmaxf(m, v);
            }
            #pragma unroll
            for (int o = 16; o; o >>= 1) m = fmaxf(m, __shfl_xor_sync(0xffffffffu, m, o));
            float s = 0.f;
            #pragma unroll
            for (int jj = 0; jj < 32; ++jj) { float e = __expf(dv[jj] - m); dv[jj] = e; s += e; }
            #pragma unroll
            for (int o = 16; o; o >>= 1) s += __shfl_xor_sync(0xffffffffu, s, o);
            #pragma unroll
            for (int jj = 0; jj < 32; ++jj) Tq[lane + jj*32] = dv[jj];
            if (lane == 0) rsum[q] = s;
        }
    }
    __syncthreads();

    // ---- Phase 3: out = P.V via split-tf32 mma ----
    {
        float acc[4][2][4];
        #pragma unroll
        for (int ng = 0; ng < 4; ++ng)
            #pragma unroll
            for (int m = 0; m < 2; ++m)
                #pragma unroll
                for (int r = 0; r < 4; ++r) acc[ng][m][r] = 0.f;

        float4 pre[8];
        #pragma unroll
        for (int l = 0; l < 8; ++l) {
            int idx = tid + l*256;
            int c = idx >> 3, t = idx & 7;
            pre[l] = *(const float4*)&Vb[(size_t)c*RS + t*4];
        }
        for (int jt = 0; jt < Ss/CT; ++jt) {
            #pragma unroll
            for (int l = 0; l < 8; ++l) {
                int idx = tid + l*256;
                int c = idx >> 3, t = idx & 7;
                BUF[(t*4+0)*VTST + c] = pre[l].x;
                BUF[(t*4+1)*VTST + c] = pre[l].y;
                BUF[(t*4+2)*VTST + c] = pre[l].z;
                BUF[(t*4+3)*VTST + c] = pre[l].w;
            }
            __syncthreads();
            if (jt + 1 < Ss/CT) {
                #pragma unroll
                for (int l = 0; l < 8; ++l) {
                    int idx = tid + l*256;
                    int c = idx >> 3, t = idx & 7;
                    pre[l] = *(const float4*)&Vb[(size_t)((jt+1)*CT + c)*RS + t*4];
                }
            }
            #pragma unroll
            for (int ks = 0; ks < 4; ++ks) {
                int cbase = jt*CT + w*32 + ks*8;
                int clocal = w*32 + ks*8;
                unsigned ah[8], al[8];
                #pragma unroll
                for (int m = 0; m < 2; ++m) {
                    float a0 = T[(m*16 + g    )*TP + cbase + td];
                    float a1 = T[(m*16 + g + 8)*TP + cbase + td];
                    float a2 = T[(m*16 + g    )*TP + cbase + td + 4];
                    float a3 = T[(m*16 + g + 8)*TP + cbase + td + 4];
                    tf32split(a0, ah[m*4+0], al[m*4+0]);
                    tf32split(a1, ah[m*4+1], al[m*4+1]);
                    tf32split(a2, ah[m*4+2], al[m*4+2]);
                    tf32split(a3, ah[m*4+3], al[m*4+3]);
                }
                #pragma unroll
                for (int ng = 0; ng < 4; ++ng) {
                    float b0f = BUF[(ng*8 + g)*VTST + clocal + td];
                    float b1f = BUF[(ng*8 + g)*VTST + clocal + td + 4];
                    unsigned bh0, bl0, bh1, bl1;
                    tf32split(b0f, bh0, bl0);
                    tf32split(b1f, bh1, bl1);
                    #pragma unroll
                    for (int m = 0; m < 2; ++m) {
                        mma_tf32(acc[ng][m], ah + m*4, bh0, bh1);
                        mma_tf32(acc[ng][m], ah + m*4, bl0, bl1);
                        mma_tf32(acc[ng][m], al + m*4, bh0, bh1);
                    }
                }
            }
            __syncthreads();
        }
        #pragma unroll
        for (int ng = 0; ng < 4; ++ng) {
            int dcol = ng*8 + 2*td;
            #pragma unroll
            for (int m = 0; m < 2; ++m) {
                int r0 = m*16 + g;
                BUF[w*REDW +  r0     *33 + dcol    ] = acc[ng][m][0];
                BUF[w*REDW +  r0     *33 + dcol + 1] = acc[ng][m][1];
                BUF[w*REDW + (r0 + 8)*33 + dcol    ] = acc[ng][m][2];
                BUF[w*REDW + (r0 + 8)*33 + dcol + 1] = acc[ng][m][3];
            }
        }
        __syncthreads();
        for (int r = tid; r < QB*Dd; r += 256) {
            int q = r >> 5, d = r & 31;
            float s = 0.f;
            #pragma unroll
            for (int wv = 0; wv < 8; ++wv) s += BUF[wv*REDW + q*33 + d];
            int i = q0 + q;
            Aout[((size_t)b*Ss + i)*Ee + h*Dd + d] = s / rsum[q];
        }
    }
}

// ---------------- host launch ----------------
extern "C" void kernel_launch(void* const* d_in, const int* in_sizes, int n_in,
                              void* d_out, int out_size)
{
    (void)in_sizes; (void)n_in; (void)out_size;
    const float* x      = (const float*)d_in[0];
    const float* Wq     = (const float*)d_in[1];
    const float* Wk     = (const float*)d_in[2];
    const float* Wv     = (const float*)d_in[3];
    const float* W_off1 = (const float*)d_in[4];
    const float* b_off1 = (const float*)d_in[5];
    const float* W_off2 = (const float*)d_in[6];
    const float* b_off2 = (const float*)d_in[7];
    const float* W_out  = (const float*)d_in[8];
    const float* b_out  = (const float*)d_in[9];
    float* out = (float*)d_out;

    float *gQKV, *gH, *gO, *gA;
    cudaGetSymbolAddress((void**)&gQKV, g_QKV);
    cudaGetSymbolAddress((void**)&gH,   g_H);
    cudaGetSymbolAddress((void**)&gO,   g_O);
    cudaGetSymbolAddress((void**)&gA,   g_A);

    const int attn_smem = (QB*TP + CT*KSST + QB*QEST + QB + QB + QB) * (int)sizeof(float);
    cudaFuncSetAttribute(attn_kernel, cudaFuncAttributeMaxDynamicSharedMemorySize, attn_smem);

    dim3 blk(256);

    qkv_mlp_kernel<<<dim3(14, TOK/64), blk>>>(x, Wq, Wk, Wv, W_off1, b_off1, gQKV, gH);
    gemm_kernel<<<dim3(1, TOK/64), blk>>>(gH, W_off2, b_off2, gO, TOK, 2*Hh, Ee/2);
    attn_kernel<<<Bb*Hh*(Ss/QB), blk, attn_smem>>>(gQKV, gO, gA);
    mma_gemm_bias<<<dim3(4, TOK/64), blk>>>(gA, W_out, b_out, out, Ee, Ee);
}

// round 11
// speedup vs baseline: 1.4032x; 1.4032x over previous
#include <cuda_runtime.h>
#include <math.h>

#define Bb 4
#define Ss 1024
#define Ee 256
#define Hh 8
#define Dd 32
#define TOK (Bb*Ss)
#define QB 32
#define RS 768          // fused QKV row stride
#define CT 256          // attention col tile
#define TP 1032         // padded T row
#define KSST 36         // K-tile smem stride (floats)
#define VTST 260        // transposed V-tile stride
#define QE2 36          // Qe stride in uint2 (pre-split hi/lo)
#define REDW 1056       // 32*33 per-warp reduction slab

// ---------------- scratch ----------------
__device__ float g_QKV[TOK*RS];
__device__ float g_H[TOK*(Ee/2)];
__device__ float g_O[TOK*2*Hh];
__device__ float g_A[TOK*Ee];

// ---------------- tf32 helpers ----------------
__device__ __forceinline__ void tf32split(float x, unsigned &hi, unsigned &lo) {
    unsigned h; asm("cvt.rna.tf32.f32 %0, %1;" : "=r"(h) : "f"(x));
    float r = x - __uint_as_float(h);
    unsigned l; asm("cvt.rna.tf32.f32 %0, %1;" : "=r"(l) : "f"(r));
    hi = h; lo = l;
}

__device__ __forceinline__ void mma_tf32(float* d, const unsigned* a, unsigned b0, unsigned b1) {
    asm volatile("mma.sync.aligned.m16n8k8.row.col.f32.tf32.tf32.f32 "
        "{%0,%1,%2,%3},{%4,%5,%6,%7},{%8,%9},{%0,%1,%2,%3};"
        : "+f"(d[0]), "+f"(d[1]), "+f"(d[2]), "+f"(d[3])
        : "r"(a[0]), "r"(a[1]), "r"(a[2]), "r"(a[3]), "r"(b0), "r"(b1));
}

// ---------------- fused QKV + MLP1 GEMM (scalar, R9-proven) ----------------
__global__ __launch_bounds__(256)
void qkv_mlp_kernel(const float* __restrict__ x,
                    const float* __restrict__ Wq, const float* __restrict__ Wk,
                    const float* __restrict__ Wv, const float* __restrict__ W1,
                    const float* __restrict__ b1,
                    float* __restrict__ QKV, float* __restrict__ Hout)
{
    __shared__ float As[16*64];
    __shared__ float Bs[16*64];
    const int tid = threadIdx.x;
    const int tx = tid & 15, ty = tid >> 4;
    const int nb = blockIdx.x;
    const int m0 = blockIdx.y * 64;

    const float* Bp; int bn0, BN;
    if (nb < 12) { Bp = (nb < 4 ? Wq : (nb < 8 ? Wk : Wv)); bn0 = (nb & 3) * 64; BN = 256; }
    else         { Bp = W1; bn0 = (nb - 12) * 64; BN = 128; }

    const int arow = tid >> 2, ak4 = (tid & 3) * 4;
    const int brow = tid >> 4, bn4 = (tid & 15) * 4;

    float acc[4][4] = {};
    float4 aPre = *(const float4*)&x[(size_t)(m0 + arow) * 256 + ak4];
    float4 bPre = *(const float4*)&Bp[(size_t)brow * BN + bn0 + bn4];

    for (int k0 = 0; k0 < 256; k0 += 16) {
        As[(ak4+0)*64 + arow] = aPre.x;
        As[(ak4+1)*64 + arow] = aPre.y;
        As[(ak4+2)*64 + arow] = aPre.z;
        As[(ak4+3)*64 + arow] = aPre.w;
        *(float4*)&Bs[brow*64 + bn4] = bPre;
        __syncthreads();
        if (k0 + 16 < 256) {
            aPre = *(const float4*)&x[(size_t)(m0 + arow) * 256 + k0 + 16 + ak4];
            bPre = *(const float4*)&Bp[(size_t)(k0 + 16 + brow) * BN + bn0 + bn4];
        }
        #pragma unroll
        for (int kk = 0; kk < 16; ++kk) {
            float4 ar = *(const float4*)&As[kk*64 + ty*4];
            float4 br = *(const float4*)&Bs[kk*64 + tx*4];
            float a4[4] = {ar.x, ar.y, ar.z, ar.w};
            float b4[4] = {br.x, br.y, br.z, br.w};
            #pragma unroll
            for (int i = 0; i < 4; ++i)
                #pragma unroll
                for (int j = 0; j < 4; ++j)
                    acc[i][j] += a4[i] * b4[j];
        }
        __syncthreads();
    }

    if (nb < 12) {
        #pragma unroll
        for (int i = 0; i < 4; ++i) {
            int m = m0 + ty*4 + i;
            #pragma unroll
            for (int j = 0; j < 4; ++j)
                QKV[(size_t)m * RS + nb*64 + tx*4 + j] = acc[i][j];
        }
    } else {
        #pragma unroll
        for (int i = 0; i < 4; ++i) {
            int m = m0 + ty*4 + i;
            #pragma unroll
            for (int j = 0; j < 4; ++j) {
                int n = (nb - 12)*64 + tx*4 + j;
                float v = acc[i][j] + b1[n];
                v = 0.5f * v * (1.0f + erff(v * 0.70710678118654752440f));
                Hout[(size_t)m * 128 + n] = v;
            }
        }
    }
}

// ---------------- generic scalar GEMM (MLP2): C = A@B + bias ----------------
__global__ __launch_bounds__(256)
void gemm_kernel(const float* __restrict__ A, const float* __restrict__ B,
                 const float* __restrict__ bias, float* __restrict__ C,
                 int M, int N, int K)
{
    __shared__ float As[16*64];
    __shared__ float Bs[16*64];
    const int tid = threadIdx.x;
    const int tx = tid & 15, ty = tid >> 4;
    const int m0 = blockIdx.y * 64;
    const int n0 = blockIdx.x * 64;

    const int arow = tid >> 2, ak4 = (tid & 3) * 4;
    const int brow = tid >> 4, bn4 = (tid & 15) * 4;

    float acc[4][4] = {};
    float4 aPre = *(const float4*)&A[(size_t)(m0 + arow) * K + ak4];
    float4 bPre = make_float4(0.f,0.f,0.f,0.f);
    if (n0 + bn4 < N) bPre = *(const float4*)&B[(size_t)brow * N + n0 + bn4];

    for (int k0 = 0; k0 < K; k0 += 16) {
        As[(ak4+0)*64 + arow] = aPre.x;
        As[(ak4+1)*64 + arow] = aPre.y;
        As[(ak4+2)*64 + arow] = aPre.z;
        As[(ak4+3)*64 + arow] = aPre.w;
        *(float4*)&Bs[brow*64 + bn4] = bPre;
        __syncthreads();
        if (k0 + 16 < K) {
            aPre = *(const float4*)&A[(size_t)(m0 + arow) * K + k0 + 16 + ak4];
            if (n0 + bn4 < N) bPre = *(const float4*)&B[(size_t)(k0 + 16 + brow) * N + n0 + bn4];
        }
        #pragma unroll
        for (int kk = 0; kk < 16; ++kk) {
            float4 ar = *(const float4*)&As[kk*64 + ty*4];
            float4 br = *(const float4*)&Bs[kk*64 + tx*4];
            float a4[4] = {ar.x, ar.y, ar.z, ar.w};
            float b4[4] = {br.x, br.y, br.z, br.w};
            #pragma unroll
            for (int i = 0; i < 4; ++i)
                #pragma unroll
                for (int j = 0; j < 4; ++j)
                    acc[i][j] += a4[i] * b4[j];
        }
        __syncthreads();
    }

    #pragma unroll
    for (int i = 0; i < 4; ++i) {
        int m = m0 + ty*4 + i;
        #pragma unroll
        for (int j = 0; j < 4; ++j) {
            int n = n0 + tx*4 + j;
            if (n < N) C[(size_t)m * N + n] = acc[i][j] + bias[n];
        }
    }
}

// ---------------- out-proj GEMM: 32x64 tiles for 2x grid (occupancy) ----------------
// N must be a multiple of 64 (N=256 here).
__global__ __launch_bounds__(256)
void gemm32_kernel(const float* __restrict__ A, const float* __restrict__ B,
                   const float* __restrict__ bias, float* __restrict__ C,
                   int N, int K)
{
    __shared__ float As[16*32];
    __shared__ float Bs[16*64];
    const int tid = threadIdx.x;
    const int tx = tid & 15, ty = tid >> 4;   // ty 0..15 -> 2 rows each
    const int m0 = blockIdx.y * 32;
    const int n0 = blockIdx.x * 64;

    const int arow = tid >> 3, ak2 = (tid & 7) * 2;   // A: 32x16, float2/thread
    const int brow = tid >> 4, bn4 = (tid & 15) * 4;  // B: 16x64, float4/thread

    float acc[2][4] = {};
    float2 aPre = *(const float2*)&A[(size_t)(m0 + arow) * K + ak2];
    float4 bPre = *(const float4*)&B[(size_t)brow * N + n0 + bn4];

    for (int k0 = 0; k0 < K; k0 += 16) {
        As[(ak2+0)*32 + arow] = aPre.x;
        As[(ak2+1)*32 + arow] = aPre.y;
        *(float4*)&Bs[brow*64 + bn4] = bPre;
        __syncthreads();
        if (k0 + 16 < K) {
            aPre = *(const float2*)&A[(size_t)(m0 + arow) * K + k0 + 16 + ak2];
            bPre = *(const float4*)&B[(size_t)(k0 + 16 + brow) * N + n0 + bn4];
        }
        #pragma unroll
        for (int kk = 0; kk < 16; ++kk) {
            float2 ar = *(const float2*)&As[kk*32 + ty*2];
            float4 br = *(const float4*)&Bs[kk*64 + tx*4];
            float a2[2] = {ar.x, ar.y};
            float b4[4] = {br.x, br.y, br.z, br.w};
            #pragma unroll
            for (int i = 0; i < 2; ++i)
                #pragma unroll
                for (int j = 0; j < 4; ++j)
                    acc[i][j] += a2[i] * b4[j];
        }
        __syncthreads();
    }

    #pragma unroll
    for (int i = 0; i < 2; ++i) {
        int m = m0 + ty*2 + i;
        #pragma unroll
        for (int j = 0; j < 4; ++j) {
            int n = n0 + tx*4 + j;
            C[(size_t)m * N + n] = acc[i][j] + bias[n];
        }
    }
}

// ---------------- fused deformable attention (tf32 MMA, pre-split Qe, tf32 P) ----------------
__global__ __launch_bounds__(256, 1)
void attn_kernel(const float* __restrict__ QKV, const float* __restrict__ OFF,
                 float* __restrict__ Aout)
{
    extern __shared__ float sm[];
    float* T    = sm;                       // 32*TP
    float* BUF  = T + QB*TP;                // CT*KSST floats (K tile / Vt tile / reduction)
    uint2* Qe2  = (uint2*)(BUF + CT*KSST);  // 32*QE2 uint2 (pre-split hi/lo Qeff)
    float* tail = (float*)(Qe2 + QB*QE2);
    float* wxs  = tail;
    float* rsum = wxs + QB;
    int*   axs  = (int*)(rsum + QB);

    const int tid = threadIdx.x;
    const int nq  = Ss / QB;
    const int bh  = blockIdx.x / nq;
    const int q0  = (blockIdx.x % nq) * QB;
    const int b   = bh / Hh;
    const int h   = bh % Hh;
    const float scale = 0.17677669529663689f;

    const float* Qb = QKV + (size_t)b*Ss*RS + h*Dd;
    const float* Kb = Qb + 256;
    const float* Vb = Qb + 512;

    const int lane = tid & 31;
    const int w    = tid >> 5;
    const int g    = lane >> 2;
    const int td   = lane & 3;

    // ---- Phase 0: Qeff (row-blended, pre-scaled), split hi/lo into smem ----
    {
        const int d = tid & 31;
        const int qq = tid >> 5;
        #pragma unroll
        for (int it = 0; it < 4; ++it) {
            int q = qq + it*8;
            int i = q0 + q;
            float ox = OFF[((size_t)(b*Ss + i)*Hh + h)*2 + 0];
            float oy = OFF[((size_t)(b*Ss + i)*Hh + h)*2 + 1];
            float fy = floorf(oy);
            float wy = oy - fy;
            int y0 = i + (int)fy, y1 = y0 + 1;
            float qv = 0.f;
            if (y0 >= 0 && y0 < Ss) qv += (1.f - wy) * Qb[(size_t)y0*RS + d];
            if (y1 >= 0 && y1 < Ss) qv += wy * Qb[(size_t)y1*RS + d];
            unsigned hh, ll;
            tf32split(qv * scale, hh, ll);
            Qe2[q*QE2 + d] = make_uint2(hh, ll);
            if (d == 0) { float fx = floorf(ox); wxs[q] = ox - fx; axs[q] = (int)fx; }
        }
    }
    __syncthreads();

    // ---- Phase 1: T = Qe . K^T via split-tf32 mma (A pre-split: no cvt in loop) ----
    {
        float4 pre[8];
        #pragma unroll
        for (int l = 0; l < 8; ++l) {
            int idx = tid + l*256;
            int c = idx >> 3, t = idx & 7;
            pre[l] = *(const float4*)&Kb[(size_t)c*RS + t*4];
        }
        for (int ct = 0; ct < Ss/CT; ++ct) {
            #pragma unroll
            for (int l = 0; l < 8; ++l) {
                int idx = tid + l*256;
                int c = idx >> 3, t = idx & 7;
                *(float4*)&BUF[c*KSST + t*4] = pre[l];
            }
            __syncthreads();
            if (ct + 1 < Ss/CT) {
                #pragma unroll
                for (int l = 0; l < 8; ++l) {
                    int idx = tid + l*256;
                    int c = idx >> 3, t = idx & 7;
                    pre[l] = *(const float4*)&Kb[(size_t)((ct+1)*CT + c)*RS + t*4];
                }
            }
            float acc[4][2][4];
            #pragma unroll
            for (int ng = 0; ng < 4; ++ng)
                #pragma unroll
                for (int m = 0; m < 2; ++m)
                    #pragma unroll
                    for (int r = 0; r < 4; ++r) acc[ng][m][r] = 0.f;

            #pragma unroll
            for (int ks = 0; ks < 4; ++ks) {
                unsigned ah[8], al[8];
                #pragma unroll
                for (int m = 0; m < 2; ++m) {
                    uint2 u0 = Qe2[(m*16 + g    )*QE2 + ks*8 + td];
                    uint2 u1 = Qe2[(m*16 + g + 8)*QE2 + ks*8 + td];
                    uint2 u2 = Qe2[(m*16 + g    )*QE2 + ks*8 + td + 4];
                    uint2 u3 = Qe2[(m*16 + g + 8)*QE2 + ks*8 + td + 4];
                    ah[m*4+0] = u0.x; al[m*4+0] = u0.y;
                    ah[m*4+1] = u1.x; al[m*4+1] = u1.y;
                    ah[m*4+2] = u2.x; al[m*4+2] = u2.y;
                    ah[m*4+3] = u3.x; al[m*4+3] = u3.y;
                }
                #pragma unroll
                for (int ng = 0; ng < 4; ++ng) {
                    int n0 = w*32 + ng*8;
                    float b0f = BUF[(n0 + g)*KSST + ks*8 + td];
                    float b1f = BUF[(n0 + g)*KSST + ks*8 + td + 4];
                    unsigned bh0, bl0, bh1, bl1;
                    tf32split(b0f, bh0, bl0);
                    tf32split(b1f, bh1, bl1);
                    #pragma unroll
                    for (int m = 0; m < 2; ++m) {
                        mma_tf32(acc[ng][m], ah + m*4, bh0, bh1);
                        mma_tf32(acc[ng][m], ah + m*4, bl0, bl1);
                        mma_tf32(acc[ng][m], al + m*4, bh0, bh1);
                    }
                }
            }
            #pragma unroll
            for (int ng = 0; ng < 4; ++ng) {
                int col = ct*CT + w*32 + ng*8 + 2*td;
                #pragma unroll
                for (int m = 0; m < 2; ++m) {
                    int r0 = m*16 + g;
                    *(float2*)&T[ r0     *TP + col] = make_float2(acc[ng][m][0], acc[ng][m][1]);
                    *(float2*)&T[(r0 + 8)*TP + col] = make_float2(acc[ng][m][2], acc[ng][m][3]);
                }
            }
            __syncthreads();
        }
    }

    // ---- Phase 2: shift/blend + softmax; probs rounded to tf32 (num & denom consistent) ----
    {
        #pragma unroll
        for (int it = 0; it < 4; ++it) {
            int q = w + it*8;
            float wx = wxs[q];
            int ax = axs[q];
            float* Tq = T + q*TP;
            float dv[32];
            float m = -1e30f;
            #pragma unroll
            for (int jj = 0; jj < 32; ++jj) {
                int j = lane + jj*32;
                int c0 = j + ax, c1 = c0 + 1;
                float t0 = (c0 >= 0 && c0 < Ss) ? Tq[c0] : 0.f;
                float t1 = (c1 >= 0 && c1 < Ss) ? Tq[c1] : 0.f;
                float v = (1.f - wx)*t0 + wx*t1;
                dv[jj] = v;
                m = fmaxf(m, v);
            }
            #pragma unroll
            for (int o = 16; o; o >>= 1) m = fmaxf(m, __shfl_xor_sync(0xffffffffu, m, o));
            float s = 0.f;
            #pragma unroll
            for (int jj = 0; jj < 32; ++jj) {
                float e = __expf(dv[jj] - m);
                unsigned er; asm("cvt.rna.tf32.f32 %0, %1;" : "=r"(er) : "f"(e));
                float ef = __uint_as_float(er);   // tf32-exact prob
                dv[jj] = ef; s += ef;
            }
            #pragma unroll
            for (int o = 16; o; o >>= 1) s += __shfl_xor_sync(0xffffffffu, s, o);
            #pragma unroll
            for (int jj = 0; jj < 32; ++jj) Tq[lane + jj*32] = dv[jj];
            if (lane == 0) rsum[q] = s;
        }
    }
    __syncthreads();

    // ---- Phase 3: out = P.V via tf32 mma (P already tf32-exact: no split, 2-term) ----
    {
        float acc[4][2][4];
        #pragma unroll
        for (int ng = 0; ng < 4; ++ng)
            #pragma unroll
            for (int m = 0; m < 2; ++m)
                #pragma unroll
                for (int r = 0; r < 4; ++r) acc[ng][m][r] = 0.f;

        float4 pre[8];
        #pragma unroll
        for (int l = 0; l < 8; ++l) {
            int idx = tid + l*256;
            int c = idx >> 3, t = idx & 7;
            pre[l] = *(const float4*)&Vb[(size_t)c*RS + t*4];
        }
        for (int jt = 0; jt < Ss/CT; ++jt) {
            #pragma unroll
            for (int l = 0; l < 8; ++l) {
                int idx = tid + l*256;
                int c = idx >> 3, t = idx & 7;
                BUF[(t*4+0)*VTST + c] = pre[l].x;
                BUF[(t*4+1)*VTST + c] = pre[l].y;
                BUF[(t*4+2)*VTST + c] = pre[l].z;
                BUF[(t*4+3)*VTST + c] = pre[l].w;
            }
            __syncthreads();
            if (jt + 1 < Ss/CT) {
                #pragma unroll
                for (int l = 0; l < 8; ++l) {
                    int idx = tid + l*256;
                    int c = idx >> 3, t = idx & 7;
                    pre[l] = *(const float4*)&Vb[(size_t)((jt+1)*CT + c)*RS + t*4];
                }
            }
            #pragma unroll
            for (int ks = 0; ks < 4; ++ks) {
                int cbase = jt*CT + w*32 + ks*8;
                int clocal = w*32 + ks*8;
                unsigned ah[8];
                #pragma unroll
                for (int m = 0; m < 2; ++m) {
                    ah[m*4+0] = __float_as_uint(T[(m*16 + g    )*TP + cbase + td]);
                    ah[m*4+1] = __float_as_uint(T[(m*16 + g + 8)*TP + cbase + td]);
                    ah[m*4+2] = __float_as_uint(T[(m*16 + g    )*TP + cbase + td + 4]);
                    ah[m*4+3] = __float_as_uint(T[(m*16 + g + 8)*TP + cbase + td + 4]);
                }
                #pragma unroll
                for (int ng = 0; ng < 4; ++ng) {
                    float b0f = BUF[(ng*8 + g)*VTST + clocal + td];
                    float b1f = BUF[(ng*8 + g)*VTST + clocal + td + 4];
                    unsigned bh0, bl0, bh1, bl1;
                    tf32split(b0f, bh0, bl0);
                    tf32split(b1f, bh1, bl1);
                    #pragma unroll
                    for (int m = 0; m < 2; ++m) {
                        mma_tf32(acc[ng][m], ah + m*4, bh0, bh1);
                        mma_tf32(acc[ng][m], ah + m*4, bl0, bl1);
                    }
                }
            }
            __syncthreads();
        }
        #pragma unroll
        for (int ng = 0; ng < 4; ++ng) {
            int dcol = ng*8 + 2*td;
            #pragma unroll
            for (int m = 0; m < 2; ++m) {
                int r0 = m*16 + g;
                BUF[w*REDW +  r0     *33 + dcol    ] = acc[ng][m][0];
                BUF[w*REDW +  r0     *33 + dcol + 1] = acc[ng][m][1];
                BUF[w*REDW + (r0 + 8)*33 + dcol    ] = acc[ng][m][2];
                BUF[w*REDW + (r0 + 8)*33 + dcol + 1] = acc[ng][m][3];
            }
        }
        __syncthreads();
        for (int r = tid; r < QB*Dd; r += 256) {
            int q = r >> 5, d = r & 31;
            float s = 0.f;
            #pragma unroll
            for (int wv = 0; wv < 8; ++wv) s += BUF[wv*REDW + q*33 + d];
            int i = q0 + q;
            Aout[((size_t)b*Ss + i)*Ee + h*Dd + d] = s / rsum[q];
        }
    }
}

// ---------------- host launch ----------------
extern "C" void kernel_launch(void* const* d_in, const int* in_sizes, int n_in,
                              void* d_out, int out_size)
{
    (void)in_sizes; (void)n_in; (void)out_size;
    const float* x      = (const float*)d_in[0];
    const float* Wq     = (const float*)d_in[1];
    const float* Wk     = (const float*)d_in[2];
    const float* Wv     = (const float*)d_in[3];
    const float* W_off1 = (const float*)d_in[4];
    const float* b_off1 = (const float*)d_in[5];
    const float* W_off2 = (const float*)d_in[6];
    const float* b_off2 = (const float*)d_in[7];
    const float* W_out  = (const float*)d_in[8];
    const float* b_out  = (const float*)d_in[9];
    float* out = (float*)d_out;

    float *gQKV, *gH, *gO, *gA;
    cudaGetSymbolAddress((void**)&gQKV, g_QKV);
    cudaGetSymbolAddress((void**)&gH,   g_H);
    cudaGetSymbolAddress((void**)&gO,   g_O);
    cudaGetSymbolAddress((void**)&gA,   g_A);

    const int attn_smem = (QB*TP + CT*KSST + QB*QE2*2 + QB + QB + QB) * (int)sizeof(float);
    cudaFuncSetAttribute(attn_kernel, cudaFuncAttributeMaxDynamicSharedMemorySize, attn_smem);

    dim3 blk(256);

    qkv_mlp_kernel<<<dim3(14, TOK/64), blk>>>(x, Wq, Wk, Wv, W_off1, b_off1, gQKV, gH);
    gemm_kernel<<<dim3(1, TOK/64), blk>>>(gH, W_off2, b_off2, gO, TOK, 2*Hh, Ee/2);
    attn_kernel<<<Bb*Hh*(Ss/QB), blk, attn_smem>>>(gQKV, gO, gA);
    gemm32_kernel<<<dim3(4, TOK/32), blk>>>(gA, W_out, b_out, out, Ee, Ee);
}

// round 12
// speedup vs baseline: 1.4494x; 1.0330x over previous
#include <cuda_runtime.h>
#include <math.h>

#define Bb 4
#define Ss 1024
#define Ee 256
#define Hh 8
#define Dd 32
#define TOK (Bb*Ss)
#define QB 32
#define RS 768          // fused QKV row stride
#define CT 256          // attention col tile
#define TP 1032         // padded T row
#define KSST 36         // K-tile smem stride (floats)
#define VTST 260        // transposed V-tile stride
#define QE2 36          // Qe stride in uint2 (pre-split hi/lo)
#define REDW 1056       // 32*33 per-warp reduction slab
#define WN 896          // fused qkv+mlp1 output width
#define GST 20          // GEMM smem tile stride (uint2 units)

// ---------------- scratch ----------------
__device__ float g_QKV[TOK*RS];
__device__ float g_H[TOK*(Ee/2)];
__device__ float g_O[TOK*2*Hh];
__device__ uint2 g_x2[TOK*Ee];      // pre-split x
__device__ uint2 g_Wt2[WN*Ee];      // pre-split fused weights, transposed [n][k]
__device__ uint2 g_Wot2[Ee*Ee];     // pre-split W_out, transposed [n][k]
__device__ uint2 g_A2[TOK*Ee];      // pre-split attention output

// ---------------- tf32 helpers ----------------
__device__ __forceinline__ void tf32split(float x, unsigned &hi, unsigned &lo) {
    unsigned h; asm("cvt.rna.tf32.f32 %0, %1;" : "=r"(h) : "f"(x));
    float r = x - __uint_as_float(h);
    unsigned l; asm("cvt.rna.tf32.f32 %0, %1;" : "=r"(l) : "f"(r));
    hi = h; lo = l;
}

__device__ __forceinline__ void mma_tf32(float* d, const unsigned* a, unsigned b0, unsigned b1) {
    asm volatile("mma.sync.aligned.m16n8k8.row.col.f32.tf32.tf32.f32 "
        "{%0,%1,%2,%3},{%4,%5,%6,%7},{%8,%9},{%0,%1,%2,%3};"
        : "+f"(d[0]), "+f"(d[1]), "+f"(d[2]), "+f"(d[3])
        : "r"(a[0]), "r"(a[1]), "r"(a[2]), "r"(a[3]), "r"(b0), "r"(b1));
}

// ---------------- split kernels (run once per launch, cheap) ----------------
__global__ __launch_bounds__(256)
void split_x_kernel(const float* __restrict__ x, uint2* __restrict__ gx)
{
    int i = blockIdx.x * 256 + threadIdx.x;
    unsigned h, l; tf32split(x[i], h, l);
    gx[i] = make_uint2(h, l);
}

// gWt[n][k]: n 0..255 Wq cols, 256..511 Wk, 512..767 Wv, 768..895 W1.
// gWot[n][k]: W_out cols. grid=WN blocks, 256 threads (k).
__global__ __launch_bounds__(256)
void split_w_kernel(const float* __restrict__ Wq, const float* __restrict__ Wk,
                    const float* __restrict__ Wv, const float* __restrict__ W1,
                    const float* __restrict__ Wo,
                    uint2* __restrict__ gWt, uint2* __restrict__ gWot)
{
    int n = blockIdx.x;
    int k = threadIdx.x;
    float v;
    if      (n < 256) v = Wq[k*256 + n];
    else if (n < 512) v = Wk[k*256 + (n - 256)];
    else if (n < 768) v = Wv[k*256 + (n - 512)];
    else              v = W1[k*128 + (n - 768)];
    unsigned h, l; tf32split(v, h, l);
    gWt[n*256 + k] = make_uint2(h, l);
    if (n < 256) {
        tf32split(Wo[k*256 + n], h, l);
        gWot[n*256 + k] = make_uint2(h, l);
    }
}

// ---------------- pre-split tf32 MMA GEMM (64x64 tile, K=256, no in-loop cvt) ----
// A2[M][256] uint2, B2t[N][256] uint2 (transposed). 8 warps: wm=(w&3)*16, wn=(w>>2)*32.
// EPI 0: qkv_mlp epilogue (col<768 -> QKV raw; else bias+gelu -> Hout)
// EPI 1: out-proj epilogue (bias -> Cout, N=256)
template<int EPI>
__global__ __launch_bounds__(256)
void mma_gemm2(const uint2* __restrict__ A2, const uint2* __restrict__ B2t,
               const float* __restrict__ b1, const float* __restrict__ bo,
               float* __restrict__ QKV, float* __restrict__ Hout,
               float* __restrict__ Cout)
{
    __shared__ uint2 As2[64*GST];
    __shared__ uint2 Bs2[64*GST];
    const int tid = threadIdx.x;
    const int lane = tid & 31;
    const int w = tid >> 5;
    const int g = lane >> 2, td = lane & 3;
    const int wm = (w & 3) * 16, wn = (w >> 2) * 32;
    const int m0 = blockIdx.y * 64;
    const int n0 = blockIdx.x * 64;

    const int row = tid >> 2;            // 0..63
    const int c4  = (tid & 3) * 4;       // 0..12 (uint2 units)

    const uint2* gA = A2  + (size_t)(m0 + row) * 256 + c4;
    const uint2* gB = B2t + (size_t)(n0 + row) * 256 + c4;

    float acc[4][4];
    #pragma unroll
    for (int ng = 0; ng < 4; ++ng)
        #pragma unroll
        for (int r = 0; r < 4; ++r) acc[ng][r] = 0.f;

    uint4 ap0 = *(const uint4*)(gA);
    uint4 ap1 = *(const uint4*)(gA + 2);
    uint4 bp0 = *(const uint4*)(gB);
    uint4 bp1 = *(const uint4*)(gB + 2);

    for (int k0 = 0; k0 < 256; k0 += 16) {
        *(uint4*)&As2[row*GST + c4]     = ap0;
        *(uint4*)&As2[row*GST + c4 + 2] = ap1;
        *(uint4*)&Bs2[row*GST + c4]     = bp0;
        *(uint4*)&Bs2[row*GST + c4 + 2] = bp1;
        __syncthreads();
        if (k0 + 16 < 256) {
            ap0 = *(const uint4*)(gA + k0 + 16);
            ap1 = *(const uint4*)(gA + k0 + 18);
            bp0 = *(const uint4*)(gB + k0 + 16);
            bp1 = *(const uint4*)(gB + k0 + 18);
        }
        #pragma unroll
        for (int ks = 0; ks < 2; ++ks) {
            unsigned ah[4], al[4];
            {
                uint2 u0 = As2[(wm + g    )*GST + ks*8 + td];
                uint2 u1 = As2[(wm + g + 8)*GST + ks*8 + td];
                uint2 u2 = As2[(wm + g    )*GST + ks*8 + td + 4];
                uint2 u3 = As2[(wm + g + 8)*GST + ks*8 + td + 4];
                ah[0] = u0.x; al[0] = u0.y;
                ah[1] = u1.x; al[1] = u1.y;
                ah[2] = u2.x; al[2] = u2.y;
                ah[3] = u3.x; al[3] = u3.y;
            }
            #pragma unroll
            for (int ng = 0; ng < 4; ++ng) {
                uint2 ub0 = Bs2[(wn + ng*8 + g)*GST + ks*8 + td];
                uint2 ub1 = Bs2[(wn + ng*8 + g)*GST + ks*8 + td + 4];
                mma_tf32(acc[ng], ah, ub0.x, ub1.x);   // hi*hi
                mma_tf32(acc[ng], ah, ub0.y, ub1.y);   // hi*lo
                mma_tf32(acc[ng], al, ub0.x, ub1.x);   // lo*hi
            }
        }
        __syncthreads();
    }

    #pragma unroll
    for (int ng = 0; ng < 4; ++ng) {
        int col = n0 + wn + ng*8 + 2*td;
        int r0  = m0 + wm + g;
        if (EPI == 0) {
            if (col < 768) {
                *(float2*)&QKV[(size_t)r0      *RS + col] = make_float2(acc[ng][0], acc[ng][1]);
                *(float2*)&QKV[(size_t)(r0 + 8)*RS + col] = make_float2(acc[ng][2], acc[ng][3]);
            } else {
                int n = col - 768;
                float bv0 = b1[n], bv1 = b1[n + 1];
                float v[4] = {acc[ng][0] + bv0, acc[ng][1] + bv1,
                              acc[ng][2] + bv0, acc[ng][3] + bv1};
                #pragma unroll
                for (int r = 0; r < 4; ++r)
                    v[r] = 0.5f * v[r] * (1.0f + erff(v[r] * 0.70710678118654752440f));
                *(float2*)&Hout[(size_t)r0      *128 + n] = make_float2(v[0], v[1]);
                *(float2*)&Hout[(size_t)(r0 + 8)*128 + n] = make_float2(v[2], v[3]);
            }
        } else {
            float bv0 = bo[col], bv1 = bo[col + 1];
            *(float2*)&Cout[(size_t)r0      *256 + col] = make_float2(acc[ng][0] + bv0, acc[ng][1] + bv1);
            *(float2*)&Cout[(size_t)(r0 + 8)*256 + col] = make_float2(acc[ng][2] + bv0, acc[ng][3] + bv1);
        }
    }
}

// ---------------- generic scalar GEMM (MLP2 only): C = A@B + bias ----------------
__global__ __launch_bounds__(256)
void gemm_kernel(const float* __restrict__ A, const float* __restrict__ B,
                 const float* __restrict__ bias, float* __restrict__ C,
                 int M, int N, int K)
{
    __shared__ float As[16*64];
    __shared__ float Bs[16*64];
    const int tid = threadIdx.x;
    const int tx = tid & 15, ty = tid >> 4;
    const int m0 = blockIdx.y * 64;
    const int n0 = blockIdx.x * 64;

    const int arow = tid >> 2, ak4 = (tid & 3) * 4;
    const int brow = tid >> 4, bn4 = (tid & 15) * 4;

    float acc[4][4] = {};
    float4 aPre = *(const float4*)&A[(size_t)(m0 + arow) * K + ak4];
    float4 bPre = make_float4(0.f,0.f,0.f,0.f);
    if (n0 + bn4 < N) bPre = *(const float4*)&B[(size_t)brow * N + n0 + bn4];

    for (int k0 = 0; k0 < K; k0 += 16) {
        As[(ak4+0)*64 + arow] = aPre.x;
        As[(ak4+1)*64 + arow] = aPre.y;
        As[(ak4+2)*64 + arow] = aPre.z;
        As[(ak4+3)*64 + arow] = aPre.w;
        *(float4*)&Bs[brow*64 + bn4] = bPre;
        __syncthreads();
        if (k0 + 16 < K) {
            aPre = *(const float4*)&A[(size_t)(m0 + arow) * K + k0 + 16 + ak4];
            if (n0 + bn4 < N) bPre = *(const float4*)&B[(size_t)(k0 + 16 + brow) * N + n0 + bn4];
        }
        #pragma unroll
        for (int kk = 0; kk < 16; ++kk) {
            float4 ar = *(const float4*)&As[kk*64 + ty*4];
            float4 br = *(const float4*)&Bs[kk*64 + tx*4];
            float a4[4] = {ar.x, ar.y, ar.z, ar.w};
            float b4[4] = {br.x, br.y, br.z, br.w};
            #pragma unroll
            for (int i = 0; i < 4; ++i)
                #pragma unroll
                for (int j = 0; j < 4; ++j)
                    acc[i][j] += a4[i] * b4[j];
        }
        __syncthreads();
    }

    #pragma unroll
    for (int i = 0; i < 4; ++i) {
        int m = m0 + ty*4 + i;
        #pragma unroll
        for (int j = 0; j < 4; ++j) {
            int n = n0 + tx*4 + j;
            if (n < N) C[(size_t)m * N + n] = acc[i][j] + bias[n];
        }
    }
}

// ---------------- fused deformable attention (tf32 MMA; R11-proven; split output) ----
__global__ __launch_bounds__(256, 1)
void attn_kernel(const float* __restrict__ QKV, const float* __restrict__ OFF,
                 uint2* __restrict__ Aout2)
{
    extern __shared__ float sm[];
    float* T    = sm;                       // 32*TP
    float* BUF  = T + QB*TP;                // CT*KSST floats
    uint2* Qe2  = (uint2*)(BUF + CT*KSST);  // 32*QE2 uint2
    float* tail = (float*)(Qe2 + QB*QE2);
    float* wxs  = tail;
    float* rsum = wxs + QB;
    int*   axs  = (int*)(rsum + QB);

    const int tid = threadIdx.x;
    const int nq  = Ss / QB;
    const int bh  = blockIdx.x / nq;
    const int q0  = (blockIdx.x % nq) * QB;
    const int b   = bh / Hh;
    const int h   = bh % Hh;
    const float scale = 0.17677669529663689f;

    const float* Qb = QKV + (size_t)b*Ss*RS + h*Dd;
    const float* Kb = Qb + 256;
    const float* Vb = Qb + 512;

    const int lane = tid & 31;
    const int w    = tid >> 5;
    const int g    = lane >> 2;
    const int td   = lane & 3;

    // ---- Phase 0 ----
    {
        const int d = tid & 31;
        const int qq = tid >> 5;
        #pragma unroll
        for (int it = 0; it < 4; ++it) {
            int q = qq + it*8;
            int i = q0 + q;
            float ox = OFF[((size_t)(b*Ss + i)*Hh + h)*2 + 0];
            float oy = OFF[((size_t)(b*Ss + i)*Hh + h)*2 + 1];
            float fy = floorf(oy);
            float wy = oy - fy;
            int y0 = i + (int)fy, y1 = y0 + 1;
            float qv = 0.f;
            if (y0 >= 0 && y0 < Ss) qv += (1.f - wy) * Qb[(size_t)y0*RS + d];
            if (y1 >= 0 && y1 < Ss) qv += wy * Qb[(size_t)y1*RS + d];
            unsigned hh, ll;
            tf32split(qv * scale, hh, ll);
            Qe2[q*QE2 + d] = make_uint2(hh, ll);
            if (d == 0) { float fx = floorf(ox); wxs[q] = ox - fx; axs[q] = (int)fx; }
        }
    }
    __syncthreads();

    // ---- Phase 1: T = Qe . K^T ----
    {
        float4 pre[8];
        #pragma unroll
        for (int l = 0; l < 8; ++l) {
            int idx = tid + l*256;
            int c = idx >> 3, t = idx & 7;
            pre[l] = *(const float4*)&Kb[(size_t)c*RS + t*4];
        }
        for (int ct = 0; ct < Ss/CT; ++ct) {
            #pragma unroll
            for (int l = 0; l < 8; ++l) {
                int idx = tid + l*256;
                int c = idx >> 3, t = idx & 7;
                *(float4*)&BUF[c*KSST + t*4] = pre[l];
            }
            __syncthreads();
            if (ct + 1 < Ss/CT) {
                #pragma unroll
                for (int l = 0; l < 8; ++l) {
                    int idx = tid + l*256;
                    int c = idx >> 3, t = idx & 7;
                    pre[l] = *(const float4*)&Kb[(size_t)((ct+1)*CT + c)*RS + t*4];
                }
            }
            float acc[4][2][4];
            #pragma unroll
            for (int ng = 0; ng < 4; ++ng)
                #pragma unroll
                for (int m = 0; m < 2; ++m)
                    #pragma unroll
                    for (int r = 0; r < 4; ++r) acc[ng][m][r] = 0.f;

            #pragma unroll
            for (int ks = 0; ks < 4; ++ks) {
                unsigned ah[8], al[8];
                #pragma unroll
                for (int m = 0; m < 2; ++m) {
                    uint2 u0 = Qe2[(m*16 + g    )*QE2 + ks*8 + td];
                    uint2 u1 = Qe2[(m*16 + g + 8)*QE2 + ks*8 + td];
                    uint2 u2 = Qe2[(m*16 + g    )*QE2 + ks*8 + td + 4];
                    uint2 u3 = Qe2[(m*16 + g + 8)*QE2 + ks*8 + td + 4];
                    ah[m*4+0] = u0.x; al[m*4+0] = u0.y;
                    ah[m*4+1] = u1.x; al[m*4+1] = u1.y;
                    ah[m*4+2] = u2.x; al[m*4+2] = u2.y;
                    ah[m*4+3] = u3.x; al[m*4+3] = u3.y;
                }
                #pragma unroll
                for (int ng = 0; ng < 4; ++ng) {
                    int n0 = w*32 + ng*8;
                    float b0f = BUF[(n0 + g)*KSST + ks*8 + td];
                    float b1f = BUF[(n0 + g)*KSST + ks*8 + td + 4];
                    unsigned bh0, bl0, bh1, bl1;
                    tf32split(b0f, bh0, bl0);
                    tf32split(b1f, bh1, bl1);
                    #pragma unroll
                    for (int m = 0; m < 2; ++m) {
                        mma_tf32(acc[ng][m], ah + m*4, bh0, bh1);
                        mma_tf32(acc[ng][m], ah + m*4, bl0, bl1);
                        mma_tf32(acc[ng][m], al + m*4, bh0, bh1);
                    }
                }
            }
            #pragma unroll
            for (int ng = 0; ng < 4; ++ng) {
                int col = ct*CT + w*32 + ng*8 + 2*td;
                #pragma unroll
                for (int m = 0; m < 2; ++m) {
                    int r0 = m*16 + g;
                    *(float2*)&T[ r0     *TP + col] = make_float2(acc[ng][m][0], acc[ng][m][1]);
                    *(float2*)&T[(r0 + 8)*TP + col] = make_float2(acc[ng][m][2], acc[ng][m][3]);
                }
            }
            __syncthreads();
        }
    }

    // ---- Phase 2: shift/blend + softmax; tf32-exact probs ----
    {
        #pragma unroll
        for (int it = 0; it < 4; ++it) {
            int q = w + it*8;
            float wx = wxs[q];
            int ax = axs[q];
            float* Tq = T + q*TP;
            float dv[32];
            float m = -1e30f;
            #pragma unroll
            for (int jj = 0; jj < 32; ++jj) {
                int j = lane + jj*32;
                int c0 = j + ax, c1 = c0 + 1;
                float t0 = (c0 >= 0 && c0 < Ss) ? Tq[c0] : 0.f;
                float t1 = (c1 >= 0 && c1 < Ss) ? Tq[c1] : 0.f;
                float v = (1.f - wx)*t0 + wx*t1;
                dv[jj] = v;
                m = fmaxf(m, v);
            }
            #pragma unroll
            for (int o = 16; o; o >>= 1) m = fmaxf(m, __shfl_xor_sync(0xffffffffu, m, o));
            float s = 0.f;
            #pragma unroll
            for (int jj = 0; jj < 32; ++jj) {
                float e = __expf(dv[jj] - m);
                unsigned er; asm("cvt.rna.tf32.f32 %0, %1;" : "=r"(er) : "f"(e));
                float ef = __uint_as_float(er);
                dv[jj] = ef; s += ef;
            }
            #pragma unroll
            for (int o = 16; o; o >>= 1) s += __shfl_xor_sync(0xffffffffu, s, o);
            #pragma unroll
            for (int jj = 0; jj < 32; ++jj) Tq[lane + jj*32] = dv[jj];
            if (lane == 0) rsum[q] = s;
        }
    }
    __syncthreads();

    // ---- Phase 3: out = P.V (P tf32-exact, 2-term) ----
    {
        float acc[4][2][4];
        #pragma unroll
        for (int ng = 0; ng < 4; ++ng)
            #pragma unroll
            for (int m = 0; m < 2; ++m)
                #pragma unroll
                for (int r = 0; r < 4; ++r) acc[ng][m][r] = 0.f;

        float4 pre[8];
        #pragma unroll
        for (int l = 0; l < 8; ++l) {
            int idx = tid + l*256;
            int c = idx >> 3, t = idx & 7;
            pre[l] = *(const float4*)&Vb[(size_t)c*RS + t*4];
        }
        for (int jt = 0; jt < Ss/CT; ++jt) {
            #pragma unroll
            for (int l = 0; l < 8; ++l) {
                int idx = tid + l*256;
                int c = idx >> 3, t = idx & 7;
                BUF[(t*4+0)*VTST + c] = pre[l].x;
                BUF[(t*4+1)*VTST + c] = pre[l].y;
                BUF[(t*4+2)*VTST + c] = pre[l].z;
                BUF[(t*4+3)*VTST + c] = pre[l].w;
            }
            __syncthreads();
            if (jt + 1 < Ss/CT) {
                #pragma unroll
                for (int l = 0; l < 8; ++l) {
                    int idx = tid + l*256;
                    int c = idx >> 3, t = idx & 7;
                    pre[l] = *(const float4*)&Vb[(size_t)((jt+1)*CT + c)*RS + t*4];
                }
            }
            #pragma unroll
            for (int ks = 0; ks < 4; ++ks) {
                int cbase = jt*CT + w*32 + ks*8;
                int clocal = w*32 + ks*8;
                unsigned ah[8];
                #pragma unroll
                for (int m = 0; m < 2; ++m) {
                    ah[m*4+0] = __float_as_uint(T[(m*16 + g    )*TP + cbase + td]);
                    ah[m*4+1] = __float_as_uint(T[(m*16 + g + 8)*TP + cbase + td]);
                    ah[m*4+2] = __float_as_uint(T[(m*16 + g    )*TP + cbase + td + 4]);
                    ah[m*4+3] = __float_as_uint(T[(m*16 + g + 8)*TP + cbase + td + 4]);
                }
                #pragma unroll
                for (int ng = 0; ng < 4; ++ng) {
                    float b0f = BUF[(ng*8 + g)*VTST + clocal + td];
                    float b1f = BUF[(ng*8 + g)*VTST + clocal + td + 4];
                    unsigned bh0, bl0, bh1, bl1;
                    tf32split(b0f, bh0, bl0);
                    tf32split(b1f, bh1, bl1);
                    #pragma unroll
                    for (int m = 0; m < 2; ++m) {
                        mma_tf32(acc[ng][m], ah + m*4, bh0, bh1);
                        mma_tf32(acc[ng][m], ah + m*4, bl0, bl1);
                    }
                }
            }
            __syncthreads();
        }
        #pragma unroll
        for (int ng = 0; ng < 4; ++ng) {
            int dcol = ng*8 + 2*td;
            #pragma unroll
            for (int m = 0; m < 2; ++m) {
                int r0 = m*16 + g;
                BUF[w*REDW +  r0     *33 + dcol    ] = acc[ng][m][0];
                BUF[w*REDW +  r0     *33 + dcol + 1] = acc[ng][m][1];
                BUF[w*REDW + (r0 + 8)*33 + dcol    ] = acc[ng][m][2];
                BUF[w*REDW + (r0 + 8)*33 + dcol + 1] = acc[ng][m][3];
            }
        }
        __syncthreads();
        for (int r = tid; r < QB*Dd; r += 256) {
            int q = r >> 5, d = r & 31;
            float s = 0.f;
            #pragma unroll
            for (int wv = 0; wv < 8; ++wv) s += BUF[wv*REDW + q*33 + d];
            int i = q0 + q;
            unsigned hh, ll;
            tf32split(s / rsum[q], hh, ll);
            Aout2[((size_t)b*Ss + i)*Ee + h*Dd + d] = make_uint2(hh, ll);
        }
    }
}

// ---------------- host launch ----------------
extern "C" void kernel_launch(void* const* d_in, const int* in_sizes, int n_in,
                              void* d_out, int out_size)
{
    (void)in_sizes; (void)n_in; (void)out_size;
    const float* x      = (const float*)d_in[0];
    const float* Wq     = (const float*)d_in[1];
    const float* Wk     = (const float*)d_in[2];
    const float* Wv     = (const float*)d_in[3];
    const float* W_off1 = (const float*)d_in[4];
    const float* b_off1 = (const float*)d_in[5];
    const float* W_off2 = (const float*)d_in[6];
    const float* b_off2 = (const float*)d_in[7];
    const float* W_out  = (const float*)d_in[8];
    const float* b_out  = (const float*)d_in[9];
    float* out = (float*)d_out;

    float *gQKV, *gH, *gO;
    uint2 *gx2, *gWt2, *gWot2, *gA2;
    cudaGetSymbolAddress((void**)&gQKV,  g_QKV);
    cudaGetSymbolAddress((void**)&gH,    g_H);
    cudaGetSymbolAddress((void**)&gO,    g_O);
    cudaGetSymbolAddress((void**)&gx2,   g_x2);
    cudaGetSymbolAddress((void**)&gWt2,  g_Wt2);
    cudaGetSymbolAddress((void**)&gWot2, g_Wot2);
    cudaGetSymbolAddress((void**)&gA2,   g_A2);

    const int attn_smem = (QB*TP + CT*KSST + QB*QE2*2 + QB + QB + QB) * (int)sizeof(float);
    cudaFuncSetAttribute(attn_kernel, cudaFuncAttributeMaxDynamicSharedMemorySize, attn_smem);

    dim3 blk(256);

    split_x_kernel<<<TOK*Ee/256, blk>>>(x, gx2);
    split_w_kernel<<<WN, blk>>>(Wq, Wk, Wv, W_off1, W_out, gWt2, gWot2);

    mma_gemm2<0><<<dim3(WN/64, TOK/64), blk>>>(gx2, gWt2, b_off1, nullptr, gQKV, gH, nullptr);
    gemm_kernel<<<dim3(1, TOK/64), blk>>>(gH, W_off2, b_off2, gO, TOK, 2*Hh, Ee/2);
    attn_kernel<<<Bb*Hh*(Ss/QB), blk, attn_smem>>>(gQKV, gO, gA2);
    mma_gemm2<1><<<dim3(Ee/64, TOK/64), blk>>>(gA2, gWot2, nullptr, b_out, nullptr, nullptr, out);
}